// round 5
// baseline (speedup 1.0000x reference)
#include <cuda_runtime.h>
#include <cstdint>

// GraphUpsamplingBlock == dense per-coarse-node 3-layer MLP:
//   H = relu(x[snd] @ W_emb[q])                (128 -> 64)
//   E = 0.25 * relu(H @ W_edge[q][2:66])       (64  -> 64)
//   O = relu(E @ W_node[128+64q : +64])        (64  -> 256)
//   out[rcv - n_coarse] = O
// Persistent CTAs, tf32 mma, coalesced X staging, balanced GEMM3 tiling.

#define NCOARSE 55552   // 248*224
#define CDIM    128
#define UDIM    64
#define NUNITS  256
#define TILE_M  128
#define NTILES  434     // NCOARSE / TILE_M
#define NTHREADS 512
#define NSLOTS  37      // grid = 4 * 37 = 148 persistent CTAs

// lead dims: all fragment arrays need ld % 8 == 4 (conflict-free ldmatrix)
#define LDX   132
#define LDW1T 132
#define LDW2T 68
#define LDW3T 68
#define LDHE  68

#define OFF_W1T 0                               // [64 n][132]   = 8448
#define OFF_W2T (OFF_W1T + UDIM*LDW1T)          // [64 n][68]    -> 8448
#define OFF_W3T (OFF_W2T + UDIM*LDW2T)          // [256 n][68]   -> 12800
#define OFF_X   (OFF_W3T + NUNITS*LDW3T)        // X[128][132] / H[128][68] -> 30208
#define OFF_E   (OFF_X + TILE_M*LDX)            // E[128][68]    -> 47104
#define SMEM_WORDS (OFF_E + TILE_M*LDHE)        // 55808 words = 223232 B

__device__ __forceinline__ uint32_t f2tf(float f) {
    uint32_t u;
    asm("cvt.rna.tf32.f32 %0, %1;" : "=r"(u) : "f"(f));
    return u;
}

__device__ __forceinline__ void mma8(float c[4], const uint32_t a[4],
                                     uint32_t b0, uint32_t b1) {
    asm volatile(
        "mma.sync.aligned.m16n8k8.row.col.f32.tf32.tf32.f32 "
        "{%0,%1,%2,%3},{%4,%5,%6,%7},{%8,%9},{%0,%1,%2,%3};"
        : "+f"(c[0]), "+f"(c[1]), "+f"(c[2]), "+f"(c[3])
        : "r"(a[0]), "r"(a[1]), "r"(a[2]), "r"(a[3]), "r"(b0), "r"(b1));
}

__device__ __forceinline__ void ldm4(uint32_t r[4], uint32_t saddr) {
    asm volatile("ldmatrix.sync.aligned.m8n8.x4.shared.b16 {%0,%1,%2,%3}, [%4];"
        : "=r"(r[0]), "=r"(r[1]), "=r"(r[2]), "=r"(r[3]) : "r"(saddr));
}

__global__ void __launch_bounds__(NTHREADS, 1)
gub_tc4_kernel(const float* __restrict__ x,
               const float* __restrict__ W_emb,
               const float* __restrict__ W_edge,
               const float* __restrict__ W_node,
               const int*   __restrict__ edge_idx,
               float* __restrict__ out)
{
    extern __shared__ uint32_t smem[];
    uint32_t* W1t = smem + OFF_W1T;
    uint32_t* W2t = smem + OFF_W2T;
    uint32_t* W3t = smem + OFF_W3T;
    uint32_t* Xs  = smem + OFF_X;     // X tile (tf32), then H (LDHE addressing)
    uint32_t* Es  = smem + OFF_E;     // E tile

    __shared__ int sndb[2][TILE_M];
    __shared__ int rcvb[2][TILE_M];

    const int tid  = threadIdx.x;
    const int q    = blockIdx.x & 3;
    const int slot = blockIdx.x >> 2;

    // ---- stage transposed weights ONCE per CTA (convert to tf32) ----
    const float* W1g = W_emb + (size_t)q * CDIM * UDIM;            // [k][n]
    for (int i = tid; i < CDIM * UDIM; i += NTHREADS)
        W1t[(i & 63) * LDW1T + (i >> 6)] = f2tf(W1g[i]);
    const float* W2g = W_edge + (size_t)q * (2 + 2 * UDIM) * UDIM + 2 * UDIM;
    for (int i = tid; i < UDIM * UDIM; i += NTHREADS)
        W2t[(i & 63) * LDW2T + (i >> 6)] = f2tf(W2g[i]);
    const float* W3g = W_node + (size_t)(CDIM + q * UDIM) * NUNITS; // [k][n]
    for (int i = tid; i < UDIM * NUNITS; i += NTHREADS)
        W3t[(i & 255) * LDW3T + (i >> 8)] = f2tf(W3g[i]);

    if (tid < TILE_M) {
        int eoff = (q * NCOARSE + slot * TILE_M + tid) * 2;
        sndb[0][tid] = edge_idx[eoff];
        rcvb[0][tid] = edge_idx[eoff + 1] - NCOARSE;
    }
    __syncthreads();

    const int lane = tid & 31;
    const int warp = tid >> 5;
    const int g    = lane >> 2;
    const int tig  = lane & 3;
    // GEMM1/2 tiling: 8 row groups of 16, 2 col halves of 32
    const int mb   = 16 * (warp & 7);
    const int nb   = 32 * (warp >> 3);
    // GEMM3 tiling: 4 row groups of 32, 4 col groups of 64
    const int mb3  = 32 * (warp & 3);
    const int cb3  = 64 * (warp >> 2);

    // ldmatrix per-lane address patterns
    const uint32_t smem_u = (uint32_t)__cvta_generic_to_shared(smem);
    const int arow  = (lane & 7) + ((lane >> 3) & 1) * 8;
    const int acol  = (lane >> 4) * 4;
    const uint32_t aX  = smem_u + 4u * (OFF_X + (mb  + arow) * LDX  + acol);
    const uint32_t aH  = smem_u + 4u * (OFF_X + (mb  + arow) * LDHE + acol);
    const uint32_t aE0 = smem_u + 4u * (OFF_E + (mb3 + arow) * LDHE + acol);
    const uint32_t aE1 = smem_u + 4u * (OFF_E + (mb3 + 16 + arow) * LDHE + acol);
    const int brow  = lane & 7;
    const int bcol  = (lane >> 3) * 4;
    const uint32_t b1a = smem_u + 4u * (OFF_W1T + brow * LDW1T + bcol);
    const uint32_t b2a = smem_u + 4u * (OFF_W2T + brow * LDW2T + bcol);
    const uint32_t b3a = smem_u + 4u * (OFF_W3T + brow * LDW3T + bcol);

    int it = 0;
    for (int t = slot; t < NTILES; t += NSLOTS, ++it) {
        const int par = it & 1;

        // ---- stage X tile: coalesced float4 gather -> tf32 smem -----------
        // (safe without a barrier: prev iter's E-ready sync guarantees all
        //  H reads done; GEMM3 only touches E/W3/out.)
        for (int i = tid; i < TILE_M * 32; i += NTHREADS) {
            int r  = i >> 5;
            int c4 = (i & 31) << 2;
            float4 v = *(const float4*)&x[(size_t)sndb[par][r] * CDIM + c4];
            uint32_t* dst = &Xs[r * LDX + c4];
            dst[0] = f2tf(v.x); dst[1] = f2tf(v.y);
            dst[2] = f2tf(v.z); dst[3] = f2tf(v.w);
        }
        __syncthreads();   // X ready

        // prefetch next tile's edge indices into the other buffer
        int t2 = t + NSLOTS;
        if (t2 < NTILES && tid < TILE_M) {
            int eoff = (q * NCOARSE + t2 * TILE_M + tid) * 2;
            sndb[par ^ 1][tid] = edge_idx[eoff];
            rcvb[par ^ 1][tid] = edge_idx[eoff + 1] - NCOARSE;
        }

        // =========== GEMM1: H = relu(X @ W1), 128x64, K=128 ================
        {
            float acc[4][4];
            #pragma unroll
            for (int nt = 0; nt < 4; nt++)
                #pragma unroll
                for (int r = 0; r < 4; r++) acc[nt][r] = 0.f;

            #pragma unroll
            for (int kp = 0; kp < 8; kp++) {
                uint32_t a0[4], a1[4];
                ldm4(a0, aX + 4u * (16 * kp));
                ldm4(a1, aX + 4u * (16 * kp + 8));
                #pragma unroll
                for (int nt = 0; nt < 4; nt++) {
                    uint32_t bf[4];
                    ldm4(bf, b1a + 4u * ((nb + 8 * nt) * LDW1T + 16 * kp));
                    mma8(acc[nt], a0, bf[0], bf[1]);
                    mma8(acc[nt], a1, bf[2], bf[3]);
                }
            }
            __syncthreads();   // all X reads done before H overwrites region
            #pragma unroll
            for (int nt = 0; nt < 4; nt++) {
                int c = nb + 8 * nt + 2 * tig;
                uint2 v0, v1;
                v0.x = f2tf(fmaxf(acc[nt][0], 0.f));
                v0.y = f2tf(fmaxf(acc[nt][1], 0.f));
                v1.x = f2tf(fmaxf(acc[nt][2], 0.f));
                v1.y = f2tf(fmaxf(acc[nt][3], 0.f));
                *(uint2*)&Xs[(mb + g)     * LDHE + c] = v0;
                *(uint2*)&Xs[(mb + g + 8) * LDHE + c] = v1;
            }
        }
        __syncthreads();   // H ready

        // =========== GEMM2: E = 0.25*relu(H @ W2), 128x64, K=64 ============
        {
            float acc[4][4];
            #pragma unroll
            for (int nt = 0; nt < 4; nt++)
                #pragma unroll
                for (int r = 0; r < 4; r++) acc[nt][r] = 0.f;

            #pragma unroll
            for (int kp = 0; kp < 4; kp++) {
                uint32_t a0[4], a1[4];
                ldm4(a0, aH + 4u * (16 * kp));
                ldm4(a1, aH + 4u * (16 * kp + 8));
                #pragma unroll
                for (int nt = 0; nt < 4; nt++) {
                    uint32_t bf[4];
                    ldm4(bf, b2a + 4u * ((nb + 8 * nt) * LDW2T + 16 * kp));
                    mma8(acc[nt], a0, bf[0], bf[1]);
                    mma8(acc[nt], a1, bf[2], bf[3]);
                }
            }
            #pragma unroll
            for (int nt = 0; nt < 4; nt++) {
                int c = nb + 8 * nt + 2 * tig;
                uint2 v0, v1;
                v0.x = f2tf(fmaxf(acc[nt][0], 0.f) * 0.25f);
                v0.y = f2tf(fmaxf(acc[nt][1], 0.f) * 0.25f);
                v1.x = f2tf(fmaxf(acc[nt][2], 0.f) * 0.25f);
                v1.y = f2tf(fmaxf(acc[nt][3], 0.f) * 0.25f);
                *(uint2*)&Es[(mb + g)     * LDHE + c] = v0;
                *(uint2*)&Es[(mb + g + 8) * LDHE + c] = v1;
            }
        }
        __syncthreads();   // E ready

        // =========== GEMM3: O = relu(E @ W3), 32m x 64n per warp ===========
        {
            uint32_t Af[2][8][4];   // 2 m-fragments x 8 k-steps
            #pragma unroll
            for (int ks = 0; ks < 8; ks++) {
                ldm4(Af[0][ks], aE0 + 4u * (8 * ks));
                ldm4(Af[1][ks], aE1 + 4u * (8 * ks));
            }
            const int r0 = rcvb[par][mb3 + g],      r1 = rcvb[par][mb3 + 8 + g];
            const int r2 = rcvb[par][mb3 + 16 + g], r3 = rcvb[par][mb3 + 24 + g];

            #pragma unroll
            for (int pass = 0; pass < 2; pass++) {
                float acc[2][4][4];
                #pragma unroll
                for (int mt = 0; mt < 2; mt++)
                    #pragma unroll
                    for (int nt = 0; nt < 4; nt++)
                        #pragma unroll
                        for (int r = 0; r < 4; r++) acc[mt][nt][r] = 0.f;

                #pragma unroll
                for (int kp = 0; kp < 4; kp++) {
                    #pragma unroll
                    for (int nt = 0; nt < 4; nt++) {
                        uint32_t bf[4];
                        ldm4(bf, b3a + 4u * ((cb3 + 32 * pass + 8 * nt) * LDW3T + 16 * kp));
                        mma8(acc[0][nt], Af[0][2 * kp],     bf[0], bf[1]);
                        mma8(acc[0][nt], Af[0][2 * kp + 1], bf[2], bf[3]);
                        mma8(acc[1][nt], Af[1][2 * kp],     bf[0], bf[1]);
                        mma8(acc[1][nt], Af[1][2 * kp + 1], bf[2], bf[3]);
                    }
                }
                #pragma unroll
                for (int mt = 0; mt < 2; mt++) {
                    int ra = mt ? r2 : r0;
                    int rb = mt ? r3 : r1;
                    #pragma unroll
                    for (int nt = 0; nt < 4; nt++) {
                        int c = cb3 + 32 * pass + 8 * nt + 2 * tig;
                        float2 v0, v1;
                        v0.x = fmaxf(acc[mt][nt][0], 0.f);
                        v0.y = fmaxf(acc[mt][nt][1], 0.f);
                        v1.x = fmaxf(acc[mt][nt][2], 0.f);
                        v1.y = fmaxf(acc[mt][nt][3], 0.f);
                        *(float2*)&out[(size_t)ra * NUNITS + c] = v0;
                        *(float2*)&out[(size_t)rb * NUNITS + c] = v1;
                    }
                }
            }
        }
        // no trailing barrier: next iter's X-ready sync fences buffer reuse
    }
}

extern "C" void kernel_launch(void* const* d_in, const int* in_sizes, int n_in,
                              void* d_out, int out_size)
{
    const float* x        = (const float*)d_in[0];
    const float* W_emb    = (const float*)d_in[1];
    const float* W_edge   = (const float*)d_in[2];
    const float* W_node   = (const float*)d_in[3];
    const int*   edge_idx = (const int*)d_in[4];
    float* out = (float*)d_out;

    size_t smem_bytes = SMEM_WORDS * sizeof(uint32_t);  // 223232
    cudaFuncSetAttribute(gub_tc4_kernel,
                         cudaFuncAttributeMaxDynamicSharedMemorySize,
                         (int)smem_bytes);

    gub_tc4_kernel<<<4 * NSLOTS, NTHREADS, smem_bytes>>>(x, W_emb, W_edge,
                                                         W_node, edge_idx, out);
}

// round 7
// speedup vs baseline: 1.2050x; 1.2050x over previous
#include <cuda_runtime.h>
#include <cuda_fp16.h>
#include <cstdint>

// GraphUpsamplingBlock == dense per-coarse-node 3-layer MLP:
//   H = relu(x[snd] @ W_emb[q])                (128 -> 64)
//   E = 0.25 * relu(H @ W_edge[q][2:66])       (64  -> 64)
//   O = relu(E @ W_node[128+64q : +64])        (64  -> 256)
//   out[rcv - n_coarse] = O
// fp16 mma.m16n8k16, per-warp-independent tiles (zero CTA barriers in loop),
// persistent CTAs, 2 CTAs/SM.

#define NCOARSE 55552   // 248*224
#define CDIM    128
#define UDIM    64
#define NUNITS  256
#define TILE_M  128
#define NTILES  434     // NCOARSE / TILE_M
#define NTHREADS 256
#define NSLOTS  74      // grid = 4 * 74 = 296 = 2 CTAs/SM * 148

// lead dims in half units: stride % 64 == 8 -> row starts spread over 16B banks
#define LDW1 136
#define LDW2 72
#define LDW3 72
#define LDHE 72

// offsets in half units
#define OFF_W1 0
#define OFF_W2 (OFF_W1 + 64*LDW1)       // 8704
#define OFF_W3 (OFF_W2 + 64*LDW2)       // 13312
#define OFF_H  (OFF_W3 + 256*LDW3)      // 31744
#define OFF_E  (OFF_H + TILE_M*LDHE)    // 40960
#define SMEM_HALFS (OFF_E + TILE_M*LDHE) // 50176 halfs = 100352 B

__device__ __forceinline__ uint32_t packh2(float lo, float hi) {
    uint32_t u;
    asm("cvt.rn.f16x2.f32 %0, %1, %2;" : "=r"(u) : "f"(hi), "f"(lo));
    return u;
}

__device__ __forceinline__ void sts32(uint32_t addr, uint32_t val) {
    asm volatile("st.shared.b32 [%0], %1;" :: "r"(addr), "r"(val));
}

__device__ __forceinline__ void mma16(float c[4], const uint32_t a[4],
                                      uint32_t b0, uint32_t b1) {
    asm volatile(
        "mma.sync.aligned.m16n8k16.row.col.f32.f16.f16.f32 "
        "{%0,%1,%2,%3},{%4,%5,%6,%7},{%8,%9},{%0,%1,%2,%3};"
        : "+f"(c[0]), "+f"(c[1]), "+f"(c[2]), "+f"(c[3])
        : "r"(a[0]), "r"(a[1]), "r"(a[2]), "r"(a[3]), "r"(b0), "r"(b1));
}

__device__ __forceinline__ void ldm4(uint32_t r[4], uint32_t saddr) {
    asm volatile("ldmatrix.sync.aligned.m8n8.x4.shared.b16 {%0,%1,%2,%3}, [%4];"
        : "=r"(r[0]), "=r"(r[1]), "=r"(r[2]), "=r"(r[3]) : "r"(saddr));
}

__global__ void __launch_bounds__(NTHREADS, 2)
gub_fp16_kernel(const float* __restrict__ x,
                const float* __restrict__ W_emb,
                const float* __restrict__ W_edge,
                const float* __restrict__ W_node,
                const int*   __restrict__ edge_idx,
                float* __restrict__ out)
{
    extern __shared__ __half smh[];

    const int tid  = threadIdx.x;
    const int q    = blockIdx.x & 3;
    const int slot = blockIdx.x >> 2;

    // ---- stage weights once per CTA, transposed (n-major, k-contiguous) ----
    const float* W1g = W_emb + (size_t)q * CDIM * UDIM;             // [k][n]
    for (int i = tid; i < CDIM * UDIM; i += NTHREADS)
        smh[OFF_W1 + (i & 63) * LDW1 + (i >> 6)] = __float2half_rn(W1g[i]);
    const float* W2g = W_edge + (size_t)q * (2 + 2 * UDIM) * UDIM + 2 * UDIM;
    for (int i = tid; i < UDIM * UDIM; i += NTHREADS)
        smh[OFF_W2 + (i & 63) * LDW2 + (i >> 6)] = __float2half_rn(W2g[i]);
    const float* W3g = W_node + (size_t)(CDIM + q * UDIM) * NUNITS; // [k][n]
    for (int i = tid; i < UDIM * NUNITS; i += NTHREADS)
        smh[OFF_W3 + (i & 255) * LDW3 + (i >> 8)] = __float2half_rn(W3g[i]);
    __syncthreads();   // the ONLY CTA barrier

    const int lane = tid & 31;
    const int warp = tid >> 5;
    const int g    = lane >> 2;
    const int tig  = lane & 3;
    const int mb   = 16 * warp;       // each warp owns rows mb..mb+15 end-to-end

    const uint32_t smem_u = (uint32_t)__cvta_generic_to_shared(smh);
    // A-fragment ldmatrix pattern (16x16 fp16 tile)
    const int arow = (lane & 7) + 8 * ((lane >> 3) & 1);
    const uint32_t aH = smem_u + 2u * (OFF_H + (mb + arow) * LDHE) + (lane >> 4) * 16;
    const uint32_t aE = smem_u + 2u * (OFF_E + (mb + arow) * LDHE) + (lane >> 4) * 16;
    // B-fragment ldmatrix pattern (16 n-rows x 16 k, gives frags for n and n+8)
    const int brow   = (lane & 7) + 8 * (lane >> 4);
    const uint32_t bh = ((lane >> 3) & 1) * 16;
    const uint32_t b1 = smem_u + 2u * OFF_W1 + brow * (2 * LDW1) + bh;
    const uint32_t b2 = smem_u + 2u * OFF_W2 + brow * (2 * LDW2) + bh;
    const uint32_t b3 = smem_u + 2u * OFF_W3 + brow * (2 * LDW3) + bh;

    // H/E store addresses (st.shared), per-lane rows mb+g and mb+g+8
    const uint32_t hst0 = smem_u + 2u * (OFF_H + (mb + g)     * LDHE + 2 * tig);
    const uint32_t hst1 = smem_u + 2u * (OFF_H + (mb + g + 8) * LDHE + 2 * tig);
    const uint32_t est0 = smem_u + 2u * (OFF_E + (mb + g)     * LDHE + 2 * tig);
    const uint32_t est1 = smem_u + 2u * (OFF_E + (mb + g + 8) * LDHE + 2 * tig);

    for (int t = slot; t < NTILES; t += NSLOTS) {
        const int erow = q * NCOARSE + t * TILE_M + mb;
        const int2 e0 = ((const int2*)edge_idx)[erow + g];
        const int2 e1 = ((const int2*)edge_idx)[erow + g + 8];
        const float* x0 = x + (size_t)e0.x * CDIM;
        const float* x1 = x + (size_t)e1.x * CDIM;
        const int r0 = e0.y - NCOARSE, r1 = e1.y - NCOARSE;

        // ========= GEMM1: H[16x64] = relu(X @ W1), K=128, A from global =====
        float acc[8][4];
        #pragma unroll
        for (int n = 0; n < 8; n++)
            #pragma unroll
            for (int r = 0; r < 4; r++) acc[n][r] = 0.f;

        #pragma unroll
        for (int kh = 0; kh < 2; kh++) {
            uint32_t Af[4][4];
            #pragma unroll
            for (int kp = 0; kp < 4; kp++) {
                int kk = 64 * kh + 16 * kp;
                float2 v;
                v = *(const float2*)&x0[kk + 2 * tig];     Af[kp][0] = packh2(v.x, v.y);
                v = *(const float2*)&x1[kk + 2 * tig];     Af[kp][1] = packh2(v.x, v.y);
                v = *(const float2*)&x0[kk + 8 + 2 * tig]; Af[kp][2] = packh2(v.x, v.y);
                v = *(const float2*)&x1[kk + 8 + 2 * tig]; Af[kp][3] = packh2(v.x, v.y);
            }
            #pragma unroll
            for (int kp = 0; kp < 4; kp++) {
                const uint32_t kb = 32u * (4 * kh + kp);
                #pragma unroll
                for (int pb = 0; pb < 4; pb++) {       // n-bases 16*pb (+0,+8)
                    uint32_t bf[4];
                    ldm4(bf, b1 + 4352u * pb + kb);    // 16*pb*LDW1*2 = 4352*pb
                    mma16(acc[2 * pb],     Af[kp], bf[0], bf[1]);
                    mma16(acc[2 * pb + 1], Af[kp], bf[2], bf[3]);
                }
            }
        }
        // store H (fp16, relu) via st.shared — own rows only
        #pragma unroll
        for (int n = 0; n < 8; n++) {
            sts32(hst0 + 16u * n, packh2(fmaxf(acc[n][0], 0.f), fmaxf(acc[n][1], 0.f)));
            sts32(hst1 + 16u * n, packh2(fmaxf(acc[n][2], 0.f), fmaxf(acc[n][3], 0.f)));
        }
        __syncwarp();

        // ========= GEMM2: E[16x64] = 0.25*relu(H @ W2), K=64 ================
        uint32_t Af2[4][4];
        #pragma unroll
        for (int kp = 0; kp < 4; kp++) ldm4(Af2[kp], aH + 32u * kp);

        #pragma unroll
        for (int n = 0; n < 8; n++)
            #pragma unroll
            for (int r = 0; r < 4; r++) acc[n][r] = 0.f;
        #pragma unroll
        for (int kp = 0; kp < 4; kp++) {
            #pragma unroll
            for (int pb = 0; pb < 4; pb++) {
                uint32_t bf[4];
                ldm4(bf, b2 + 2304u * pb + 32u * kp);  // 16*pb*LDW2*2 = 2304*pb
                mma16(acc[2 * pb],     Af2[kp], bf[0], bf[1]);
                mma16(acc[2 * pb + 1], Af2[kp], bf[2], bf[3]);
            }
        }
        #pragma unroll
        for (int n = 0; n < 8; n++) {
            sts32(est0 + 16u * n, packh2(fmaxf(acc[n][0], 0.f) * 0.25f,
                                         fmaxf(acc[n][1], 0.f) * 0.25f));
            sts32(est1 + 16u * n, packh2(fmaxf(acc[n][2], 0.f) * 0.25f,
                                         fmaxf(acc[n][3], 0.f) * 0.25f));
        }
        __syncwarp();

        // ========= GEMM3: O[16x256] = relu(E @ W3), K=64, scatter ===========
        uint32_t Af3[4][4];
        #pragma unroll
        for (int kp = 0; kp < 4; kp++) ldm4(Af3[kp], aE + 32u * kp);

        float* o0 = out + (size_t)r0 * NUNITS;
        float* o1 = out + (size_t)r1 * NUNITS;

        #pragma unroll
        for (int pass = 0; pass < 4; pass++) {
            const int cb = 64 * pass;
            #pragma unroll
            for (int n = 0; n < 8; n++)
                #pragma unroll
                for (int r = 0; r < 4; r++) acc[n][r] = 0.f;
            #pragma unroll
            for (int kp = 0; kp < 4; kp++) {
                #pragma unroll
                for (int pb = 0; pb < 4; pb++) {
                    uint32_t bf[4];
                    ldm4(bf, b3 + 9216u * pass + 2304u * pb + 32u * kp);
                    mma16(acc[2 * pb],     Af3[kp], bf[0], bf[1]);
                    mma16(acc[2 * pb + 1], Af3[kp], bf[2], bf[3]);
                }
            }
            #pragma unroll
            for (int n = 0; n < 8; n++) {
                int c = cb + 8 * n + 2 * tig;
                float2 v0, v1;
                v0.x = fmaxf(acc[n][0], 0.f); v0.y = fmaxf(acc[n][1], 0.f);
                v1.x = fmaxf(acc[n][2], 0.f); v1.y = fmaxf(acc[n][3], 0.f);
                *(float2*)&o0[c] = v0;
                *(float2*)&o1[c] = v1;
            }
        }
        // no barrier: next iteration touches only this warp's own H/E rows
    }
}

extern "C" void kernel_launch(void* const* d_in, const int* in_sizes, int n_in,
                              void* d_out, int out_size)
{
    const float* x        = (const float*)d_in[0];
    const float* W_emb    = (const float*)d_in[1];
    const float* W_edge   = (const float*)d_in[2];
    const float* W_node   = (const float*)d_in[3];
    const int*   edge_idx = (const int*)d_in[4];
    float* out = (float*)d_out;

    size_t smem_bytes = SMEM_HALFS * sizeof(__half);  // 100352
    cudaFuncSetAttribute(gub_fp16_kernel,
                         cudaFuncAttributeMaxDynamicSharedMemorySize,
                         (int)smem_bytes);

    gub_fp16_kernel<<<4 * NSLOTS, NTHREADS, smem_bytes>>>(x, W_emb, W_edge,
                                                          W_node, edge_idx, out);
}

// round 8
// speedup vs baseline: 1.8337x; 1.5217x over previous
#include <cuda_runtime.h>
#include <cuda_fp16.h>
#include <cstdint>

// GraphUpsamplingBlock == dense per-coarse-node 3-layer MLP:
//   H = relu(x[snd] @ W_emb[q])                (128 -> 64)
//   E = 0.25 * relu(H @ W_edge[q][2:66])       (64  -> 64)
//   O = relu(E @ W_node[128+64q : +64])        (64  -> 256)
//   out[rcv - n_coarse] = O
// fp16 mma, per-warp tiles, H/E passed in REGISTERS (C-frag == A-frag layout),
// coalesced epilogue via per-warp smem transpose. Persistent CTAs, 2 CTAs/SM.

#define NCOARSE 55552   // 248*224
#define CDIM    128
#define UDIM    64
#define NUNITS  256
#define TILE_M  128
#define NTILES  434     // NCOARSE / TILE_M
#define NTHREADS 256
#define NSLOTS  74      // grid = 4 * 74 = 296 = 2 CTAs/SM * 148

// weight lead dims (halfs): byte stride % 128 == 16 -> conflict-free ldmatrix
#define LDW1 136
#define LDW2 72
#define LDW3 72
#define OFF_W1 0
#define OFF_W2 (OFF_W1 + 64*LDW1)        // 8704
#define OFF_W3 (OFF_W2 + 64*LDW2)        // 13312
#define W_HALFS (OFF_W3 + 256*LDW3)      // 31744 halfs = 63488 B

#define LDO 68                            // epilogue buffer lead dim (floats)
#define OBUF_PER_WARP (16*LDO)            // 1088 floats = 4352 B
#define SMEM_BYTES (W_HALFS*2 + 8*OBUF_PER_WARP*4)   // 63488 + 34816 = 98304

__device__ __forceinline__ uint32_t packh2(float lo, float hi) {
    uint32_t u;
    asm("cvt.rn.f16x2.f32 %0, %1, %2;" : "=r"(u) : "f"(hi), "f"(lo));
    return u;
}
__device__ __forceinline__ uint32_t prelu2(float lo, float hi) {
    return packh2(fmaxf(lo, 0.f), fmaxf(hi, 0.f));
}

__device__ __forceinline__ void mma16(float c[4], const uint32_t a[4],
                                      uint32_t b0, uint32_t b1) {
    asm volatile(
        "mma.sync.aligned.m16n8k16.row.col.f32.f16.f16.f32 "
        "{%0,%1,%2,%3},{%4,%5,%6,%7},{%8,%9},{%0,%1,%2,%3};"
        : "+f"(c[0]), "+f"(c[1]), "+f"(c[2]), "+f"(c[3])
        : "r"(a[0]), "r"(a[1]), "r"(a[2]), "r"(a[3]), "r"(b0), "r"(b1));
}

__device__ __forceinline__ void ldm4(uint32_t r[4], uint32_t saddr) {
    asm volatile("ldmatrix.sync.aligned.m8n8.x4.shared.b16 {%0,%1,%2,%3}, [%4];"
        : "=r"(r[0]), "=r"(r[1]), "=r"(r[2]), "=r"(r[3]) : "r"(saddr));
}

__global__ void __launch_bounds__(NTHREADS, 2)
gub_fp16r_kernel(const float* __restrict__ x,
                 const float* __restrict__ W_emb,
                 const float* __restrict__ W_edge,
                 const float* __restrict__ W_node,
                 const int*   __restrict__ edge_idx,
                 float* __restrict__ out)
{
    extern __shared__ __half smh[];

    const int tid  = threadIdx.x;
    const int q    = blockIdx.x & 3;
    const int slot = blockIdx.x >> 2;

    // ---- stage weights once per CTA, transposed (n-major, k-contiguous) ----
    const float* W1g = W_emb + (size_t)q * CDIM * UDIM;             // [k][n]
    for (int i = tid; i < CDIM * UDIM; i += NTHREADS)
        smh[OFF_W1 + (i & 63) * LDW1 + (i >> 6)] = __float2half_rn(W1g[i]);
    const float* W2g = W_edge + (size_t)q * (2 + 2 * UDIM) * UDIM + 2 * UDIM;
    for (int i = tid; i < UDIM * UDIM; i += NTHREADS)
        smh[OFF_W2 + (i & 63) * LDW2 + (i >> 6)] = __float2half_rn(W2g[i]);
    const float* W3g = W_node + (size_t)(CDIM + q * UDIM) * NUNITS; // [k][n]
    for (int i = tid; i < UDIM * NUNITS; i += NTHREADS)
        smh[OFF_W3 + (i & 255) * LDW3 + (i >> 8)] = __float2half_rn(W3g[i]);
    __syncthreads();   // the ONLY CTA barrier

    const int lane = tid & 31;
    const int warp = tid >> 5;
    const int g    = lane >> 2;
    const int tig  = lane & 3;
    const int mb   = 16 * warp;       // each warp owns rows mb..mb+15 end-to-end

    const uint32_t smem_u = (uint32_t)__cvta_generic_to_shared(smh);
    // B-fragment ldmatrix pattern
    const int brow   = (lane & 7) + 8 * (lane >> 4);
    const uint32_t bh = ((lane >> 3) & 1) * 16;
    const uint32_t b1 = smem_u + 2u * OFF_W1 + brow * (2 * LDW1) + bh;
    const uint32_t b2 = smem_u + 2u * OFF_W2 + brow * (2 * LDW2) + bh;
    const uint32_t b3 = smem_u + 2u * OFF_W3 + brow * (2 * LDW3) + bh;

    // per-warp epilogue transpose buffer
    float* obuf = reinterpret_cast<float*>(smh + W_HALFS) + warp * OBUF_PER_WARP;
    const int hi8  = (lane >> 4) * 8;       // epilogue read row offset
    const int col4 = (lane & 15) * 4;       // epilogue read col

    for (int t = slot; t < NTILES; t += NSLOTS) {
        const int erow = q * NCOARSE + t * TILE_M + mb;
        const int2 e0 = ((const int2*)edge_idx)[erow + g];
        const int2 e1 = ((const int2*)edge_idx)[erow + g + 8];
        const float* x0 = x + (size_t)e0.x * CDIM;
        const float* x1 = x + (size_t)e1.x * CDIM;
        const int r0 = e0.y - NCOARSE, r1 = e1.y - NCOARSE;

        // epilogue row indices: iteration j covers rows mb+j (lanes<16) & mb+j+8
        int rsel[8];
        #pragma unroll
        for (int j = 0; j < 8; j++) {
            int ra = __shfl_sync(0xffffffffu, r0, 4 * j);
            int rb = __shfl_sync(0xffffffffu, r1, 4 * j);
            rsel[j] = (lane < 16) ? ra : rb;
        }

        float acc[8][4];

        // ========= GEMM1: H[16x64] = relu(X @ W1), K=128, A from global =====
        #pragma unroll
        for (int n = 0; n < 8; n++)
            #pragma unroll
            for (int r = 0; r < 4; r++) acc[n][r] = 0.f;

        #pragma unroll
        for (int kh = 0; kh < 2; kh++) {
            uint32_t Af[4][4];
            #pragma unroll
            for (int kp = 0; kp < 4; kp++) {
                int kk = 64 * kh + 16 * kp;
                float2 v;
                v = *(const float2*)&x0[kk + 2 * tig];     Af[kp][0] = packh2(v.x, v.y);
                v = *(const float2*)&x1[kk + 2 * tig];     Af[kp][1] = packh2(v.x, v.y);
                v = *(const float2*)&x0[kk + 8 + 2 * tig]; Af[kp][2] = packh2(v.x, v.y);
                v = *(const float2*)&x1[kk + 8 + 2 * tig]; Af[kp][3] = packh2(v.x, v.y);
            }
            #pragma unroll
            for (int kp = 0; kp < 4; kp++) {
                const uint32_t kb = 32u * (4 * kh + kp);
                #pragma unroll
                for (int pb = 0; pb < 4; pb++) {
                    uint32_t bf[4];
                    ldm4(bf, b1 + 4352u * pb + kb);    // 16*pb*LDW1*2
                    mma16(acc[2 * pb],     Af[kp], bf[0], bf[1]);
                    mma16(acc[2 * pb + 1], Af[kp], bf[2], bf[3]);
                }
            }
        }

        // H C-frags -> GEMM2 A-frags IN REGISTERS (C layout == A layout)
        uint32_t Af2[4][4];
        #pragma unroll
        for (int kp = 0; kp < 4; kp++) {
            Af2[kp][0] = prelu2(acc[2*kp][0],     acc[2*kp][1]);
            Af2[kp][1] = prelu2(acc[2*kp][2],     acc[2*kp][3]);
            Af2[kp][2] = prelu2(acc[2*kp+1][0],   acc[2*kp+1][1]);
            Af2[kp][3] = prelu2(acc[2*kp+1][2],   acc[2*kp+1][3]);
        }

        // ========= GEMM2: E[16x64] = 0.25*relu(H @ W2), K=64 ================
        #pragma unroll
        for (int n = 0; n < 8; n++)
            #pragma unroll
            for (int r = 0; r < 4; r++) acc[n][r] = 0.f;
        #pragma unroll
        for (int kp = 0; kp < 4; kp++) {
            #pragma unroll
            for (int pb = 0; pb < 4; pb++) {
                uint32_t bf[4];
                ldm4(bf, b2 + 2304u * pb + 32u * kp);  // 16*pb*LDW2*2
                mma16(acc[2 * pb],     Af2[kp], bf[0], bf[1]);
                mma16(acc[2 * pb + 1], Af2[kp], bf[2], bf[3]);
            }
        }

        // E C-frags -> GEMM3 A-frags in registers (0.25 * relu folded in)
        uint32_t Af3[4][4];
        #pragma unroll
        for (int kp = 0; kp < 4; kp++) {
            Af3[kp][0] = packh2(fmaxf(acc[2*kp][0],   0.f) * 0.25f,
                                fmaxf(acc[2*kp][1],   0.f) * 0.25f);
            Af3[kp][1] = packh2(fmaxf(acc[2*kp][2],   0.f) * 0.25f,
                                fmaxf(acc[2*kp][3],   0.f) * 0.25f);
            Af3[kp][2] = packh2(fmaxf(acc[2*kp+1][0], 0.f) * 0.25f,
                                fmaxf(acc[2*kp+1][1], 0.f) * 0.25f);
            Af3[kp][3] = packh2(fmaxf(acc[2*kp+1][2], 0.f) * 0.25f,
                                fmaxf(acc[2*kp+1][3], 0.f) * 0.25f);
        }

        // ========= GEMM3: O[16x256] = relu(E @ W3), K=64, coalesced scatter =
        #pragma unroll
        for (int pass = 0; pass < 4; pass++) {
            const int cb = 64 * pass;
            #pragma unroll
            for (int n = 0; n < 8; n++)
                #pragma unroll
                for (int r = 0; r < 4; r++) acc[n][r] = 0.f;
            #pragma unroll
            for (int kp = 0; kp < 4; kp++) {
                #pragma unroll
                for (int pb = 0; pb < 4; pb++) {
                    uint32_t bf[4];
                    ldm4(bf, b3 + 9216u * pass + 2304u * pb + 32u * kp);
                    mma16(acc[2 * pb],     Af3[kp], bf[0], bf[1]);
                    mma16(acc[2 * pb + 1], Af3[kp], bf[2], bf[3]);
                }
            }
            // transpose through warp-private smem, then coalesced STG.128
            #pragma unroll
            for (int n = 0; n < 8; n++) {
                *(float2*)&obuf[g * LDO + 8 * n + 2 * tig] =
                    make_float2(fmaxf(acc[n][0], 0.f), fmaxf(acc[n][1], 0.f));
                *(float2*)&obuf[(g + 8) * LDO + 8 * n + 2 * tig] =
                    make_float2(fmaxf(acc[n][2], 0.f), fmaxf(acc[n][3], 0.f));
            }
            __syncwarp();
            #pragma unroll
            for (int j = 0; j < 8; j++) {
                float4 v = *(const float4*)&obuf[(j + hi8) * LDO + col4];
                *(float4*)&out[(size_t)rsel[j] * NUNITS + cb + col4] = v;
            }
            __syncwarp();
        }
    }
}

extern "C" void kernel_launch(void* const* d_in, const int* in_sizes, int n_in,
                              void* d_out, int out_size)
{
    const float* x        = (const float*)d_in[0];
    const float* W_emb    = (const float*)d_in[1];
    const float* W_edge   = (const float*)d_in[2];
    const float* W_node   = (const float*)d_in[3];
    const int*   edge_idx = (const int*)d_in[4];
    float* out = (float*)d_out;

    cudaFuncSetAttribute(gub_fp16r_kernel,
                         cudaFuncAttributeMaxDynamicSharedMemorySize,
                         SMEM_BYTES);

    gub_fp16r_kernel<<<4 * NSLOTS, NTHREADS, SMEM_BYTES>>>(x, W_emb, W_edge,
                                                           W_node, edge_idx, out);
}

// round 9
// speedup vs baseline: 2.0170x; 1.1000x over previous
#include <cuda_runtime.h>
#include <cuda_fp16.h>
#include <cstdint>

// GraphUpsamplingBlock == dense per-coarse-node 3-layer MLP:
//   H = relu(x[snd] @ W_emb[q])                (128 -> 64)
//   E = 0.25 * relu(H @ W_edge[q][2:66])       (64  -> 64)
//   O = relu(E @ W_node[128+64q : +64])        (64  -> 256)
//   out[rcv - n_coarse] = O
// fp16 mma, per-warp 32-row tiles, H/E in registers, coalesced X staging,
// 2-tile-amortized B fragments, coalesced epilogue. 2 CTAs/SM.

#define NCOARSE 55552   // 248*224
#define CDIM    128
#define UDIM    64
#define NUNITS  256
#define CTA_ROWS 256    // 8 warps * 32 rows
#define NTILES  217     // NCOARSE / CTA_ROWS (exact)
#define NTHREADS 256
#define NSLOTS  74      // grid = 4 * 74 = 296 = 2 CTAs/SM * 148

// weight lead dims (halfs): byte stride % 128 == 16 -> conflict-free ldmatrix
#define LDW1 136
#define LDW2 72
#define LDW3 72
#define OFF_W1 0
#define OFF_W2 (OFF_W1 + 64*LDW1)        // 8704
#define OFF_W3 (OFF_W2 + 64*LDW2)        // 13312
#define W_HALFS (OFF_W3 + 256*LDW3)      // 31744 halfs
#define W_BYTES (W_HALFS*2)              // 63488 B

// per-warp staging buffer: X fp16 [16][136] = 4352 B  (aliased: epi [16][68] f32)
#define WBUF_BYTES 4352
#define SMEM_BYTES (W_BYTES + 8*WBUF_BYTES)   // 98304

__device__ __forceinline__ uint32_t packh2(float lo, float hi) {
    uint32_t u;
    asm("cvt.rn.f16x2.f32 %0, %1, %2;" : "=r"(u) : "f"(hi), "f"(lo));
    return u;
}
__device__ __forceinline__ uint32_t prelu2(float lo, float hi) {
    return packh2(fmaxf(lo, 0.f), fmaxf(hi, 0.f));
}
__device__ __forceinline__ void sts64u(uint32_t addr, uint32_t a, uint32_t b) {
    asm volatile("st.shared.v2.b32 [%0], {%1,%2};" :: "r"(addr), "r"(a), "r"(b));
}
__device__ __forceinline__ void sts64f(uint32_t addr, float a, float b) {
    asm volatile("st.shared.v2.f32 [%0], {%1,%2};" :: "r"(addr), "f"(a), "f"(b));
}
__device__ __forceinline__ void lds128f(float4& v, uint32_t addr) {
    asm volatile("ld.shared.v4.f32 {%0,%1,%2,%3}, [%4];"
        : "=f"(v.x), "=f"(v.y), "=f"(v.z), "=f"(v.w) : "r"(addr));
}
__device__ __forceinline__ void mma16(float c[4], const uint32_t a[4],
                                      uint32_t b0, uint32_t b1) {
    asm volatile(
        "mma.sync.aligned.m16n8k16.row.col.f32.f16.f16.f32 "
        "{%0,%1,%2,%3},{%4,%5,%6,%7},{%8,%9},{%0,%1,%2,%3};"
        : "+f"(c[0]), "+f"(c[1]), "+f"(c[2]), "+f"(c[3])
        : "r"(a[0]), "r"(a[1]), "r"(a[2]), "r"(a[3]), "r"(b0), "r"(b1));
}
__device__ __forceinline__ void ldm4(uint32_t r[4], uint32_t saddr) {
    asm volatile("ldmatrix.sync.aligned.m8n8.x4.shared.b16 {%0,%1,%2,%3}, [%4];"
        : "=r"(r[0]), "=r"(r[1]), "=r"(r[2]), "=r"(r[3]) : "r"(saddr));
}

__global__ void __launch_bounds__(NTHREADS, 2)
gub_fp16s_kernel(const float* __restrict__ x,
                 const float* __restrict__ W_emb,
                 const float* __restrict__ W_edge,
                 const float* __restrict__ W_node,
                 const int*   __restrict__ edge_idx,
                 float* __restrict__ out)
{
    extern __shared__ __half smh[];

    const int tid  = threadIdx.x;
    const int q    = blockIdx.x & 3;
    const int slot = blockIdx.x >> 2;

    // ---- stage weights once per CTA, transposed (n-major, k-contiguous) ----
    const float* W1g = W_emb + (size_t)q * CDIM * UDIM;             // [k][n]
    for (int i = tid; i < CDIM * UDIM; i += NTHREADS)
        smh[OFF_W1 + (i & 63) * LDW1 + (i >> 6)] = __float2half_rn(W1g[i]);
    const float* W2g = W_edge + (size_t)q * (2 + 2 * UDIM) * UDIM + 2 * UDIM;
    for (int i = tid; i < UDIM * UDIM; i += NTHREADS)
        smh[OFF_W2 + (i & 63) * LDW2 + (i >> 6)] = __float2half_rn(W2g[i]);
    const float* W3g = W_node + (size_t)(CDIM + q * UDIM) * NUNITS; // [k][n]
    for (int i = tid; i < UDIM * NUNITS; i += NTHREADS)
        smh[OFF_W3 + (i & 255) * LDW3 + (i >> 8)] = __float2half_rn(W3g[i]);
    __syncthreads();   // the ONLY CTA barrier

    const int lane = tid & 31;
    const int warp = tid >> 5;
    const int g    = lane >> 2;
    const int tig  = lane & 3;

    const uint32_t smem_u = (uint32_t)__cvta_generic_to_shared(smh);
    // B-fragment ldmatrix pattern
    const int brow   = (lane & 7) + 8 * (lane >> 4);
    const uint32_t bh = ((lane >> 3) & 1) * 16;
    const uint32_t b1 = smem_u + 2u * OFF_W1 + brow * (2 * LDW1) + bh;
    const uint32_t b2 = smem_u + 2u * OFF_W2 + brow * (2 * LDW2) + bh;
    const uint32_t b3 = smem_u + 2u * OFF_W3 + brow * (2 * LDW3) + bh;

    // per-warp staging buffer (X fp16 / epilogue f32)
    const uint32_t wbuf = smem_u + W_BYTES + warp * WBUF_BYTES;
    // A-frag ldmatrix pattern on staged X: row = lane&15, 16B col = lane>>4
    const uint32_t aXs  = wbuf + (uint32_t)(lane & 15) * 272u + (uint32_t)(lane >> 4) * 16u;
    const int hi8  = (lane >> 4) * 8;
    const int col4 = (lane & 15) * 4;
    const int rsh  = (lane >> 4) * 8;     // epilogue shfl row offset

    for (int t = slot; t < NTILES; t += NSLOTS) {
        const int rowbase = t * CTA_ROWS + warp * 32;
        const int2 e = ((const int2*)edge_idx)[q * NCOARSE + rowbase + lane];

        uint32_t Af2[2][4][4];
        float acc2[2][8][4];

        // ===== GEMM1 per 16-row tile: H = relu(X @ W1), K=128 ==============
        #pragma unroll
        for (int tt = 0; tt < 2; tt++) {
            // stage X rows coalesced (LDG.128 -> fp16 smem)
            #pragma unroll
            for (int i = 0; i < 16; i++) {
                int srow = __shfl_sync(0xffffffffu, e.x, 16 * tt + i);
                float4 v = *(const float4*)&x[(size_t)srow * CDIM + lane * 4];
                sts64u(wbuf + i * 272u + lane * 8u,
                       packh2(v.x, v.y), packh2(v.z, v.w));
            }
            __syncwarp();
            uint32_t Af[8][4];
            #pragma unroll
            for (int kp = 0; kp < 8; kp++) ldm4(Af[kp], aXs + 32u * kp);
            __syncwarp();   // frags in regs before buffer is re-staged

            float (*acc)[4] = acc2[tt];
            #pragma unroll
            for (int n = 0; n < 8; n++)
                #pragma unroll
                for (int r = 0; r < 4; r++) acc[n][r] = 0.f;
            #pragma unroll
            for (int kp = 0; kp < 8; kp++) {
                #pragma unroll
                for (int pb = 0; pb < 4; pb++) {
                    uint32_t bf[4];
                    ldm4(bf, b1 + 4352u * pb + 32u * kp);   // 16*pb*LDW1*2
                    mma16(acc[2 * pb],     Af[kp], bf[0], bf[1]);
                    mma16(acc[2 * pb + 1], Af[kp], bf[2], bf[3]);
                }
            }
            // H C-frags -> GEMM2 A-frags in registers
            #pragma unroll
            for (int kp = 0; kp < 4; kp++) {
                Af2[tt][kp][0] = prelu2(acc[2*kp][0],   acc[2*kp][1]);
                Af2[tt][kp][1] = prelu2(acc[2*kp][2],   acc[2*kp][3]);
                Af2[tt][kp][2] = prelu2(acc[2*kp+1][0], acc[2*kp+1][1]);
                Af2[tt][kp][3] = prelu2(acc[2*kp+1][2], acc[2*kp+1][3]);
            }
        }

        // ===== GEMM2 (both tiles, shared B): E = 0.25*relu(H @ W2) =========
        #pragma unroll
        for (int tt = 0; tt < 2; tt++)
            #pragma unroll
            for (int n = 0; n < 8; n++)
                #pragma unroll
                for (int r = 0; r < 4; r++) acc2[tt][n][r] = 0.f;
        #pragma unroll
        for (int kp = 0; kp < 4; kp++) {
            #pragma unroll
            for (int pb = 0; pb < 4; pb++) {
                uint32_t bf[4];
                ldm4(bf, b2 + 2304u * pb + 32u * kp);       // 16*pb*LDW2*2
                mma16(acc2[0][2 * pb],     Af2[0][kp], bf[0], bf[1]);
                mma16(acc2[0][2 * pb + 1], Af2[0][kp], bf[2], bf[3]);
                mma16(acc2[1][2 * pb],     Af2[1][kp], bf[0], bf[1]);
                mma16(acc2[1][2 * pb + 1], Af2[1][kp], bf[2], bf[3]);
            }
        }
        // E C-frags -> GEMM3 A-frags (0.25 * relu folded)
        uint32_t Af3[2][4][4];
        #pragma unroll
        for (int tt = 0; tt < 2; tt++)
            #pragma unroll
            for (int kp = 0; kp < 4; kp++) {
                Af3[tt][kp][0] = packh2(fmaxf(acc2[tt][2*kp][0],   0.f) * 0.25f,
                                        fmaxf(acc2[tt][2*kp][1],   0.f) * 0.25f);
                Af3[tt][kp][1] = packh2(fmaxf(acc2[tt][2*kp][2],   0.f) * 0.25f,
                                        fmaxf(acc2[tt][2*kp][3],   0.f) * 0.25f);
                Af3[tt][kp][2] = packh2(fmaxf(acc2[tt][2*kp+1][0], 0.f) * 0.25f,
                                        fmaxf(acc2[tt][2*kp+1][1], 0.f) * 0.25f);
                Af3[tt][kp][3] = packh2(fmaxf(acc2[tt][2*kp+1][2], 0.f) * 0.25f,
                                        fmaxf(acc2[tt][2*kp+1][3], 0.f) * 0.25f);
            }

        // ===== GEMM3 (both tiles, shared B): O = relu(E @ W3), scatter =====
        #pragma unroll
        for (int pass = 0; pass < 4; pass++) {
            const int cb = 64 * pass;
            #pragma unroll
            for (int tt = 0; tt < 2; tt++)
                #pragma unroll
                for (int n = 0; n < 8; n++)
                    #pragma unroll
                    for (int r = 0; r < 4; r++) acc2[tt][n][r] = 0.f;
            #pragma unroll
            for (int kp = 0; kp < 4; kp++) {
                #pragma unroll
                for (int pb = 0; pb < 4; pb++) {
                    uint32_t bf[4];
                    ldm4(bf, b3 + 9216u * pass + 2304u * pb + 32u * kp);
                    mma16(acc2[0][2 * pb],     Af3[0][kp], bf[0], bf[1]);
                    mma16(acc2[0][2 * pb + 1], Af3[0][kp], bf[2], bf[3]);
                    mma16(acc2[1][2 * pb],     Af3[1][kp], bf[0], bf[1]);
                    mma16(acc2[1][2 * pb + 1], Af3[1][kp], bf[2], bf[3]);
                }
            }
            // per-tile epilogue: smem transpose then coalesced STG.128
            #pragma unroll
            for (int tt = 0; tt < 2; tt++) {
                float (*acc)[4] = acc2[tt];
                #pragma unroll
                for (int n = 0; n < 8; n++) {
                    sts64f(wbuf + g * 272u + n * 32u + tig * 8u,
                           fmaxf(acc[n][0], 0.f), fmaxf(acc[n][1], 0.f));
                    sts64f(wbuf + (g + 8) * 272u + n * 32u + tig * 8u,
                           fmaxf(acc[n][2], 0.f), fmaxf(acc[n][3], 0.f));
                }
                __syncwarp();
                #pragma unroll
                for (int j = 0; j < 8; j++) {
                    int rcv = __shfl_sync(0xffffffffu, e.y, 16 * tt + j + rsh)
                              - NCOARSE;
                    float4 v;
                    lds128f(v, wbuf + (j + hi8) * 272u + col4 * 4u);
                    *(float4*)&out[(size_t)rcv * NUNITS + cb + col4] = v;
                }
                __syncwarp();
            }
        }
    }
}

extern "C" void kernel_launch(void* const* d_in, const int* in_sizes, int n_in,
                              void* d_out, int out_size)
{
    const float* x        = (const float*)d_in[0];
    const float* W_emb    = (const float*)d_in[1];
    const float* W_edge   = (const float*)d_in[2];
    const float* W_node   = (const float*)d_in[3];
    const int*   edge_idx = (const int*)d_in[4];
    float* out = (float*)d_out;

    cudaFuncSetAttribute(gub_fp16s_kernel,
                         cudaFuncAttributeMaxDynamicSharedMemorySize,
                         SMEM_BYTES);

    gub_fp16s_kernel<<<4 * NSLOTS, NTHREADS, SMEM_BYTES>>>(x, W_emb, W_edge,
                                                           W_node, edge_idx, out);
}